// round 15
// baseline (speedup 1.0000x reference)
#include <cuda_runtime.h>
#include <cuda_bf16.h>

typedef unsigned long long ull;
typedef unsigned int uint;
typedef unsigned short ushort_t;

static constexpr int IMG   = 128;
static constexpr int NPIX  = IMG * IMG;      // 16384
static constexpr int CH    = 64;
static constexpr int NHEAD = 8;
static constexpr int HIDN  = 128;
static constexpr float LNEPS  = 1e-5f;
static constexpr float QSCALE = 0.35355339059327373f;   // 8^-0.5

// ---------------- scratch ----------------
__device__ __align__(16) ushort_t g_qb [NHEAD * NPIX * 8];   // bf16
__device__ __align__(16) ushort_t g_kb [NHEAD * NPIX * 8];   // bf16
__device__ __align__(16) ushort_t g_vb [NHEAD * NPIX * 8];   // bf16
__device__ __align__(16) ushort_t g_attb[CH * NPIX];         // bf16

// ---------------- helpers ----------------
#define FMA2(acc, a, b) asm("fma.rn.f32x2 %0, %1, %2, %0;" : "+l"(acc) : "l"(a), "l"(b))

__device__ __forceinline__ ull pk(float lo, float hi) {
    ull r; asm("mov.b64 %0, {%1, %2};" : "=l"(r) : "f"(lo), "f"(hi)); return r;
}
__device__ __forceinline__ float2 upk(ull v) {
    float2 r; asm("mov.b64 {%0, %1}, %2;" : "=f"(r.x), "=f"(r.y) : "l"(v)); return r;
}
__device__ __forceinline__ uint packbf(float a, float b) {
    __nv_bfloat162 h = __floats2bfloat162_rn(a, b);
    return *reinterpret_cast<uint*>(&h);
}
__device__ __forceinline__ ushort_t bfbits(float v) {
    __nv_bfloat16 b = __float2bfloat16_rn(v);
    return *reinterpret_cast<ushort_t*>(&b);
}
__device__ __forceinline__ ull b2u(uint u) {
    return pk(__uint_as_float(u << 16), __uint_as_float(u & 0xffff0000u));
}
__device__ __forceinline__ uint sptr(const void* p) {
    return (uint)__cvta_generic_to_shared(p);
}
__device__ __forceinline__ void ldsm_x4(uint &r0, uint &r1, uint &r2, uint &r3, uint addr) {
    asm volatile("ldmatrix.sync.aligned.m8n8.x4.shared.b16 {%0,%1,%2,%3}, [%4];"
                 : "=r"(r0), "=r"(r1), "=r"(r2), "=r"(r3) : "r"(addr));
}
__device__ __forceinline__ void ldsm_x2t(uint &r0, uint &r1, uint addr) {
    asm volatile("ldmatrix.sync.aligned.m8n8.x2.trans.shared.b16 {%0,%1}, [%2];"
                 : "=r"(r0), "=r"(r1) : "r"(addr));
}
__device__ __forceinline__ void mma16816(float* c, const uint* a, uint b0, uint b1) {
    asm volatile("mma.sync.aligned.m16n8k16.row.col.f32.bf16.bf16.f32 "
                 "{%0,%1,%2,%3}, {%4,%5,%6,%7}, {%8,%9}, {%0,%1,%2,%3};"
                 : "+f"(c[0]), "+f"(c[1]), "+f"(c[2]), "+f"(c[3])
                 : "r"(a[0]), "r"(a[1]), "r"(a[2]), "r"(a[3]), "r"(b0), "r"(b1));
}
__device__ __forceinline__ void stage_w4(ushort_t* dst, const float* src) {
    float4 w = *reinterpret_cast<const float4*>(src);
    uint2 u; u.x = packbf(w.x, w.y); u.y = packbf(w.z, w.w);
    *reinterpret_cast<uint2*>(dst) = u;
}

// =================================================================
// Kernel A: LN1 -> QKV MMA GEMM -> qLN/kLN -> q/k/v bf16
// R14 parallel prologue; q now stored bf16
// =================================================================
static constexpr int SMEM_A = 192 * 68 * 4;   // 52224 (gemm phase 36864 aliased)

__global__ void __launch_bounds__(384, 2)
kA(const float* __restrict__ x, const float* __restrict__ n1w, const float* __restrict__ n1b,
   const float* __restrict__ qkvw, const float* __restrict__ qkvb,
   const float* __restrict__ qnw, const float* __restrict__ qnb,
   const float* __restrict__ knw, const float* __restrict__ knb)
{
    extern __shared__ float sm[];
    ushort_t* wbf  = reinterpret_cast<ushort_t*>(sm);          // [192][72]
    ushort_t* actb = wbf + 192 * 72;                           // [64][72]
    float*    stage = sm;                                      // [192][68] aliased
    const int tid = threadIdx.x;
    const int p0 = blockIdx.x * 64;

    if (tid >= 256) {
        const int t2 = tid - 256;
        #pragma unroll
        for (int t = 0; t < 24; t++) {
            int idx = (t2 + t * 128) * 4;
            int o = idx >> 6, c = idx & 63;
            stage_w4(&wbf[o * 72 + c], &qkvw[idx]);
        }
    } else {
        const int s = tid & 3, px = tid >> 2;
        const int p = p0 + px;
        float xv[16];
        float sum = 0.f, sq = 0.f;
        #pragma unroll
        for (int j = 0; j < 16; j++) {
            float v = x[(s * 16 + j) * NPIX + p];
            xv[j] = v; sum += v; sq += v * v;
        }
        sum += __shfl_xor_sync(0xffffffffu, sum, 1);
        sum += __shfl_xor_sync(0xffffffffu, sum, 2);
        sq  += __shfl_xor_sync(0xffffffffu, sq, 1);
        sq  += __shfl_xor_sync(0xffffffffu, sq, 2);
        float mean = sum * (1.f / 64);
        float inv = rsqrtf(sq * (1.f / 64) - mean * mean + LNEPS);
        #pragma unroll
        for (int j = 0; j < 16; j++) {
            int c = s * 16 + j;
            actb[c * 72 + px] = bfbits((xv[j] - mean) * inv * n1w[c] + n1b[c]);
        }
    }
    __syncthreads();

    const int wid = tid >> 5, lane = tid & 31;
    const int gid = lane >> 2, tig = lane & 3;
    const int q4 = lane >> 3, r4 = lane & 7;
    const int lr = lane & 15;
    const int m0 = wid * 16;

    uint a[4][4];
    #pragma unroll
    for (int ks = 0; ks < 4; ks++) {
        int arow = m0 + r4 + ((q4 & 1) << 3);
        int acol = ks * 16 + ((q4 >> 1) << 3);
        ldsm_x4(a[ks][0], a[ks][1], a[ks][2], a[ks][3], sptr(&wbf[arow * 72 + acol]));
    }
    float c[8][4];
    #pragma unroll
    for (int nt = 0; nt < 8; nt++)
        #pragma unroll
        for (int i = 0; i < 4; i++) c[nt][i] = 0.f;
    #pragma unroll
    for (int nt = 0; nt < 8; nt++) {
        #pragma unroll
        for (int ks = 0; ks < 4; ks++) {
            uint b0, b1;
            ldsm_x2t(b0, b1, sptr(&actb[(ks * 16 + lr) * 72 + nt * 8]));
            mma16816(c[nt], a[ks], b0, b1);
        }
    }
    __syncthreads();

    #pragma unroll
    for (int nt = 0; nt < 8; nt++) {
        int col = nt * 8 + 2 * tig;
        *reinterpret_cast<float2*>(&stage[(m0 + gid) * 68 + col])     = make_float2(c[nt][0], c[nt][1]);
        *reinterpret_cast<float2*>(&stage[(m0 + 8 + gid) * 68 + col]) = make_float2(c[nt][2], c[nt][3]);
    }
    __syncthreads();

    // epilogue: warps 0-3 -> Q, 4-7 -> K, 8-11 -> V.  2 lanes/px, 32 ch each.
    const int grp = wid >> 2;           // 0=q, 1=k, 2=v
    const int t2 = tid & 127;
    const int s = t2 & 1, px = t2 >> 1;
    const int p = p0 + px;
    const int base = grp * 64 + s * 32;

    float vv[32];
    if (grp == 2) {
        #pragma unroll
        for (int j = 0; j < 32; j++)
            vv[j] = stage[(base + j) * 68 + px] + qkvb[base + j];
    } else {
        float sum = 0.f, sq = 0.f;
        #pragma unroll
        for (int j = 0; j < 32; j++) {
            float v = stage[(base + j) * 68 + px] + qkvb[base + j];
            vv[j] = v; sum += v; sq += v * v;
        }
        sum += __shfl_xor_sync(0xffffffffu, sum, 1);
        sq  += __shfl_xor_sync(0xffffffffu, sq, 1);
        float mean = sum * (1.f / 64);
        float inv = rsqrtf(sq * (1.f / 64) - mean * mean + LNEPS);
        if (grp == 0) {
            #pragma unroll
            for (int j = 0; j < 32; j++) {
                int ch = s * 32 + j;
                vv[j] = ((vv[j] - mean) * inv * qnw[ch] + qnb[ch]) * QSCALE;
            }
        } else {
            #pragma unroll
            for (int j = 0; j < 32; j++) {
                int ch = s * 32 + j;
                vv[j] = (vv[j] - mean) * inv * knw[ch] + knb[ch];
            }
        }
    }
    ushort_t* dst = (grp == 0) ? g_qb : (grp == 1) ? g_kb : g_vb;
    #pragma unroll
    for (int h4 = 0; h4 < 4; h4++) {
        int h8 = s * 4 + h4;
        uint4 u;
        u.x = packbf(vv[h4*8+0], vv[h4*8+1]);
        u.y = packbf(vv[h4*8+2], vv[h4*8+3]);
        u.z = packbf(vv[h4*8+4], vv[h4*8+5]);
        u.w = packbf(vv[h4*8+6], vv[h4*8+7]);
        *reinterpret_cast<uint4*>(&dst[(h8 * NPIX + p) * 8]) = u;
    }
}

// =================================================================
// Kernel B: neighborhood attention.  256 threads, lane-pair split.
// q now bf16 (unpacked once per thread).
// =================================================================
static constexpr int HS_B = 67;
static constexpr int PL_B = 44 * HS_B;
static constexpr int SMEM_B = 2 * PL_B * 16;          // 94336 B

__device__ __forceinline__ int bswz(int c) { return c ^ (((c >> 4) & 1) << 2); }

__global__ void __launch_bounds__(256, 2)
kB()
{
    extern __shared__ uint4 smu[];
    const int tile = blockIdx.x, head = blockIdx.y;
    const int th0 = (tile >> 2) * 16, tw0 = (tile & 3) * 32;
    const int tid = threadIdx.x;
    const ushort_t* kg = g_kb + head * (NPIX * 8);
    const ushort_t* vg = g_vb + head * (NPIX * 8);

    for (int e = tid; e < 2 * 44 * 60; e += 256) {
        int arr = (e >= 44 * 60) ? 1 : 0;
        int i = e - arr * (44 * 60);
        int r = i / 60, col = i - r * 60;
        int hh = min(max(th0 - 16 + r, 0), 127);
        int ww = min(max(tw0 - 16 + col, 0), 127);
        const ushort_t* src = arr ? vg : kg;
        smu[arr * PL_B + r * HS_B + bswz(col)] =
            *reinterpret_cast<const uint4*>(src + (hh * 128 + ww) * 8);
    }
    __syncthreads();

    const int quad = tid >> 1;
    const int half = tid & 1;
    const int qy   = quad >> 3;
    const int qx8  = quad & 7;
    const int wloc = (qx8 & 3) + ((qx8 >> 2) << 4);
    const int h  = th0 + qy;
    const int wb = tw0 + wloc;

    ulonglong2 qA[4], qB[4];
    #pragma unroll
    for (int t = 0; t < 4; t++) {
        uint4 qu = *reinterpret_cast<const uint4*>(&g_qb[(head * NPIX + h * 128 + wb + 4 * t) * 8]);
        qA[t].x = b2u(qu.x); qA[t].y = b2u(qu.y);
        qB[t].x = b2u(qu.z); qB[t].y = b2u(qu.w);
    }

    float l[4] = {0.f, 0.f, 0.f, 0.f};
    ull acc2[4][4];
    #pragma unroll
    for (int t = 0; t < 4; t++)
        #pragma unroll
        for (int i = 0; i < 4; i++) acc2[t][i] = 0ull;

    #pragma unroll
    for (int ah = 0; ah < 4; ah++) {
        int a = half * 4 + ah;
        int oh = 4 * a - 16;
        bool vr = (unsigned)(h + oh) < 128u;
        int rbase = (qy + 16 + oh) * HS_B;
        #pragma unroll
        for (int s = 0; s < 11; s++) {
            int off = rbase + bswz(wloc + 4 * s);
            bool ok = vr && ((unsigned)(wb + 4 * s - 16) < 128u);
            uint4 ku = smu[off];
            uint4 vu = smu[PL_B + off];
            ull kp0 = b2u(ku.x), kp1 = b2u(ku.y), kp2 = b2u(ku.z), kp3 = b2u(ku.w);
            ull vp0 = b2u(vu.x), vp1 = b2u(vu.y), vp2 = b2u(vu.z), vp3 = b2u(vu.w);
            #pragma unroll
            for (int t = 0; t < 4; t++) {
                if (t > s || t < s - 7) continue;
                ull s2 = 0ull;
                FMA2(s2, kp0, qA[t].x);
                FMA2(s2, kp1, qA[t].y);
                FMA2(s2, kp2, qB[t].x);
                FMA2(s2, kp3, qB[t].y);
                float2 sf = upk(s2);
                float sc = ok ? (sf.x + sf.y) : -1e30f;
                float ee = __expf(sc);
                l[t] += ee;
                ull e2 = pk(ee, ee);
                FMA2(acc2[t][0], vp0, e2);
                FMA2(acc2[t][1], vp1, e2);
                FMA2(acc2[t][2], vp2, e2);
                FMA2(acc2[t][3], vp3, e2);
            }
        }
    }

    #pragma unroll
    for (int t = 0; t < 4; t++) {
        float lt = l[t] + __shfl_xor_sync(0xffffffffu, l[t], 1);
        float rl = 1.0f / lt;
        int p = h * 128 + wb + 4 * t;
        #pragma unroll
        for (int i = 0; i < 4; i++) {
            float2 f = upk(acc2[t][i]);
            f.x += __shfl_xor_sync(0xffffffffu, f.x, 1);
            f.y += __shfl_xor_sync(0xffffffffu, f.y, 1);
            if (half == 0) {
                g_attb[(head * 8 + 2 * i)     * NPIX + p] = bfbits(f.x * rl);
                g_attb[(head * 8 + 2 * i + 1) * NPIX + p] = bfbits(f.y * rl);
            }
        }
    }
}

// =================================================================
// Kernel CDE: proj+LN2 -> fc1+LN+SiLU -> fc2+residual, fused.
// R13 upfront staging; x1 kept in smem (no gmem round-trip)
// =================================================================
static constexpr int OFF_W1  = 0;                 // bf16 [64][72]   9216
static constexpr int OFF_W2  = 9216;              // bf16 [128][72] 18432
static constexpr int OFF_W3  = 27648;             // bf16 [64][136] 17408
static constexpr int OFF_ACT = 45056;             // bf16 [128][72] 18432
static constexpr int OFF_STG = 63488;             // fp32 [128][66] 33792
static constexpr int OFF_X1  = 97280;             // fp32 [64][66]  16896
static constexpr int SMEM_F  = 114176;            // 111.5 KB; 2/SM = 223 KB

__global__ void __launch_bounds__(256, 2)
kCDE(const float* __restrict__ x,
     const float* __restrict__ projw, const float* __restrict__ projb,
     const float* __restrict__ g1, const float* __restrict__ n2w, const float* __restrict__ n2b,
     const float* __restrict__ fc1w, const float* __restrict__ fc1b,
     const float* __restrict__ mnw, const float* __restrict__ mnb,
     const float* __restrict__ fc2w, const float* __restrict__ fc2b,
     const float* __restrict__ g2, float* __restrict__ out)
{
    extern __shared__ char smc[];
    ushort_t* w1  = reinterpret_cast<ushort_t*>(smc + OFF_W1);
    ushort_t* w2  = reinterpret_cast<ushort_t*>(smc + OFF_W2);
    ushort_t* w3  = reinterpret_cast<ushort_t*>(smc + OFF_W3);
    ushort_t* act = reinterpret_cast<ushort_t*>(smc + OFF_ACT);
    float*    stg = reinterpret_cast<float*>(smc + OFF_STG);
    float*    x1s = reinterpret_cast<float*>(smc + OFF_X1);
    const int tid = threadIdx.x;
    const int p0 = blockIdx.x * 64;

    #pragma unroll
    for (int t = 0; t < 4; t++) {
        int idx = (tid + t * 256) * 4;
        int o = idx >> 6, c = idx & 63;
        stage_w4(&w1[o * 72 + c], &projw[idx]);
    }
    #pragma unroll
    for (int t = 0; t < 8; t++) {
        int idx = (tid + t * 256) * 4;
        int o = idx >> 6, c = idx & 63;
        stage_w4(&w2[o * 72 + c], &fc1w[idx]);
    }
    #pragma unroll
    for (int t = 0; t < 8; t++) {
        int idx = (tid + t * 256) * 4;
        int o = idx >> 7, c = idx & 127;
        stage_w4(&w3[o * 136 + c], &fc2w[idx]);
    }
    #pragma unroll
    for (int t = 0; t < 2; t++) {
        int i = tid + t * 256;
        int c = i >> 3, u = i & 7;
        *reinterpret_cast<uint4*>(&act[c * 72 + u * 8]) =
            *reinterpret_cast<const uint4*>(&g_attb[c * NPIX + p0 + u * 8]);
    }
    __syncthreads();

    const int wid = tid >> 5, lane = tid & 31;
    const int gid = lane >> 2, tig = lane & 3;
    const int q4 = lane >> 3, r4 = lane & 7;
    const int lr = lane & 15;

    // ================= GEMM1: proj =================
    {
        const int ot = wid & 3, nh = wid >> 2;
        const int m0 = ot * 16;
        uint a[4][4];
        #pragma unroll
        for (int ks = 0; ks < 4; ks++) {
            int arow = m0 + r4 + ((q4 & 1) << 3);
            int acol = ks * 16 + ((q4 >> 1) << 3);
            ldsm_x4(a[ks][0], a[ks][1], a[ks][2], a[ks][3], sptr(&w1[arow * 72 + acol]));
        }
        float c[4][4];
        #pragma unroll
        for (int nt = 0; nt < 4; nt++)
            #pragma unroll
            for (int i = 0; i < 4; i++) c[nt][i] = 0.f;
        #pragma unroll
        for (int nt = 0; nt < 4; nt++) {
            int ntg = nh * 4 + nt;
            #pragma unroll
            for (int ks = 0; ks < 4; ks++) {
                uint b0, b1;
                ldsm_x2t(b0, b1, sptr(&act[(ks * 16 + lr) * 72 + ntg * 8]));
                mma16816(c[nt], a[ks], b0, b1);
            }
        }
        __syncthreads();
        #pragma unroll
        for (int nt = 0; nt < 4; nt++) {
            int col = (nh * 4 + nt) * 8 + 2 * tig;
            *reinterpret_cast<float2*>(&stg[(m0 + gid) * 66 + col])     = make_float2(c[nt][0], c[nt][1]);
            *reinterpret_cast<float2*>(&stg[(m0 + 8 + gid) * 66 + col]) = make_float2(c[nt][2], c[nt][3]);
        }
        __syncthreads();
    }

    // ============ Epilogue1: x1 (smem) + LN2 ============
    {
        const int s = tid & 3, px = tid >> 2;
        const int p = p0 + px;
        float vv[16];
        float sum = 0.f, sq = 0.f;
        #pragma unroll
        for (int j = 0; j < 16; j++) {
            int ch = s * 16 + j;
            float v = x[ch * NPIX + p] + g1[ch] * (stg[ch * 66 + px] + projb[ch]);
            x1s[ch * 66 + px] = v;
            vv[j] = v; sum += v; sq += v * v;
        }
        sum += __shfl_xor_sync(0xffffffffu, sum, 1);
        sum += __shfl_xor_sync(0xffffffffu, sum, 2);
        sq  += __shfl_xor_sync(0xffffffffu, sq, 1);
        sq  += __shfl_xor_sync(0xffffffffu, sq, 2);
        float mean = sum * (1.f / 64);
        float inv = rsqrtf(sq * (1.f / 64) - mean * mean + LNEPS);
        #pragma unroll
        for (int j = 0; j < 16; j++) {
            int ch = s * 16 + j;
            act[ch * 72 + px] = bfbits((vv[j] - mean) * inv * n2w[ch] + n2b[ch]);
        }
        __syncthreads();
    }

    // ================= GEMM2: fc1 =================
    {
        const int m0 = wid * 16;
        uint a[4][4];
        #pragma unroll
        for (int ks = 0; ks < 4; ks++) {
            int arow = m0 + r4 + ((q4 & 1) << 3);
            int acol = ks * 16 + ((q4 >> 1) << 3);
            ldsm_x4(a[ks][0], a[ks][1], a[ks][2], a[ks][3], sptr(&w2[arow * 72 + acol]));
        }
        float c[8][4];
        #pragma unroll
        for (int nt = 0; nt < 8; nt++)
            #pragma unroll
            for (int i = 0; i < 4; i++) c[nt][i] = 0.f;
        #pragma unroll
        for (int nt = 0; nt < 8; nt++) {
            #pragma unroll
            for (int ks = 0; ks < 4; ks++) {
                uint b0, b1;
                ldsm_x2t(b0, b1, sptr(&act[(ks * 16 + lr) * 72 + nt * 8]));
                mma16816(c[nt], a[ks], b0, b1);
            }
        }
        __syncthreads();
        #pragma unroll
        for (int nt = 0; nt < 8; nt++) {
            int col = nt * 8 + 2 * tig;
            *reinterpret_cast<float2*>(&stg[(m0 + gid) * 66 + col])     = make_float2(c[nt][0], c[nt][1]);
            *reinterpret_cast<float2*>(&stg[(m0 + 8 + gid) * 66 + col]) = make_float2(c[nt][2], c[nt][3]);
        }
        __syncthreads();
    }

    // ============ Epilogue2: LN(128) + SiLU ============
    {
        const int s = tid & 3, px = tid >> 2;
        float vv[32];
        float sum = 0.f, sq = 0.f;
        #pragma unroll
        for (int j = 0; j < 32; j++) {
            int ch = s * 32 + j;
            float v = stg[ch * 66 + px] + fc1b[ch];
            vv[j] = v; sum += v; sq += v * v;
        }
        sum += __shfl_xor_sync(0xffffffffu, sum, 1);
        sum += __shfl_xor_sync(0xffffffffu, sum, 2);
        sq  += __shfl_xor_sync(0xffffffffu, sq, 1);
        sq  += __shfl_xor_sync(0xffffffffu, sq, 2);
        float mean = sum * (1.f / 128);
        float inv = rsqrtf(sq * (1.f / 128) - mean * mean + LNEPS);
        #pragma unroll
        for (int j = 0; j < 32; j++) {
            int ch = s * 32 + j;
            float hh = (vv[j] - mean) * inv * mnw[ch] + mnb[ch];
            act[ch * 72 + px] = bfbits(hh / (1.f + __expf(-hh)));
        }
        __syncthreads();
    }

    // ======== GEMM3: fc2 + residual epilogue (x1 from smem) ========
    {
        const int ot = wid & 3, nh = wid >> 2;
        const int m0 = ot * 16;
        uint a[8][4];
        #pragma unroll
        for (int ks = 0; ks < 8; ks++) {
            int arow = m0 + r4 + ((q4 & 1) << 3);
            int acol = ks * 16 + ((q4 >> 1) << 3);
            ldsm_x4(a[ks][0], a[ks][1], a[ks][2], a[ks][3], sptr(&w3[arow * 136 + acol]));
        }
        float c[4][4];
        #pragma unroll
        for (int nt = 0; nt < 4; nt++)
            #pragma unroll
            for (int i = 0; i < 4; i++) c[nt][i] = 0.f;
        #pragma unroll
        for (int nt = 0; nt < 4; nt++) {
            int ntg = nh * 4 + nt;
            #pragma unroll
            for (int ks = 0; ks < 8; ks++) {
                uint b0, b1;
                ldsm_x2t(b0, b1, sptr(&act[(ks * 16 + lr) * 72 + ntg * 8]));
                mma16816(c[nt], a[ks], b0, b1);
            }
        }
        const int ch0 = m0 + gid, ch1 = ch0 + 8;
        const float fb0 = fc2b[ch0], gg0 = g2[ch0];
        const float fb1 = fc2b[ch1], gg1 = g2[ch1];
        #pragma unroll
        for (int nt = 0; nt < 4; nt++) {
            int pl = (nh * 4 + nt) * 8 + 2 * tig;
            int p = p0 + pl;
            float2 x0 = *reinterpret_cast<const float2*>(&x1s[ch0 * 66 + pl]);
            float2 x1 = *reinterpret_cast<const float2*>(&x1s[ch1 * 66 + pl]);
            float2 o0 = make_float2(x0.x + gg0 * (c[nt][0] + fb0), x0.y + gg0 * (c[nt][1] + fb0));
            float2 o1 = make_float2(x1.x + gg1 * (c[nt][2] + fb1), x1.y + gg1 * (c[nt][3] + fb1));
            *reinterpret_cast<float2*>(&out[ch0 * NPIX + p]) = o0;
            *reinterpret_cast<float2*>(&out[ch1 * NPIX + p]) = o1;
        }
    }
}

// =================================================================
extern "C" void kernel_launch(void* const* d_in, const int* in_sizes, int n_in,
                              void* d_out, int out_size)
{
    const float* x     = (const float*)d_in[0];
    const float* n1w   = (const float*)d_in[1];
    const float* n1b   = (const float*)d_in[2];
    const float* qkvw  = (const float*)d_in[3];
    const float* qkvb  = (const float*)d_in[4];
    const float* qnw   = (const float*)d_in[5];
    const float* qnb   = (const float*)d_in[6];
    const float* knw   = (const float*)d_in[7];
    const float* knb   = (const float*)d_in[8];
    const float* projw = (const float*)d_in[9];
    const float* projb = (const float*)d_in[10];
    const float* g1    = (const float*)d_in[11];
    const float* n2w   = (const float*)d_in[12];
    const float* n2b   = (const float*)d_in[13];
    const float* fc1w  = (const float*)d_in[14];
    const float* fc1b  = (const float*)d_in[15];
    const float* mnw   = (const float*)d_in[16];
    const float* mnb   = (const float*)d_in[17];
    const float* fc2w  = (const float*)d_in[18];
    const float* fc2b  = (const float*)d_in[19];
    const float* g2    = (const float*)d_in[20];
    float* out = (float*)d_out;

    cudaFuncSetAttribute(kA,   cudaFuncAttributeMaxDynamicSharedMemorySize, SMEM_A);
    cudaFuncSetAttribute(kB,   cudaFuncAttributeMaxDynamicSharedMemorySize, SMEM_B);
    cudaFuncSetAttribute(kCDE, cudaFuncAttributeMaxDynamicSharedMemorySize, SMEM_F);

    kA<<<256, 384, SMEM_A>>>(x, n1w, n1b, qkvw, qkvb, qnw, qnb, knw, knb);
    kB<<<dim3(32, 8), 256, SMEM_B>>>();
    kCDE<<<256, 256, SMEM_F>>>(x, projw, projb, g1, n2w, n2b,
                               fc1w, fc1b, mnw, mnb, fc2w, fc2b, g2, out);
}

// round 16
// speedup vs baseline: 1.0456x; 1.0456x over previous
#include <cuda_runtime.h>
#include <cuda_bf16.h>

typedef unsigned long long ull;
typedef unsigned int uint;
typedef unsigned short ushort_t;

static constexpr int IMG   = 128;
static constexpr int NPIX  = IMG * IMG;      // 16384
static constexpr int CH    = 64;
static constexpr int NHEAD = 8;
static constexpr int HIDN  = 128;
static constexpr float LNEPS  = 1e-5f;
static constexpr float QSCALE = 0.35355339059327373f;   // 8^-0.5

// ---------------- scratch ----------------
__device__ __align__(16) ushort_t g_qb [NHEAD * NPIX * 8];   // bf16
__device__ __align__(16) ushort_t g_kb [NHEAD * NPIX * 8];   // bf16
__device__ __align__(16) ushort_t g_vb [NHEAD * NPIX * 8];   // bf16
__device__ __align__(16) ushort_t g_attb[CH * NPIX];         // bf16
__device__ __align__(16) float    g_x1 [CH * NPIX];

// ---------------- helpers ----------------
#define FMA2(acc, a, b) asm("fma.rn.f32x2 %0, %1, %2, %0;" : "+l"(acc) : "l"(a), "l"(b))

__device__ __forceinline__ ull pk(float lo, float hi) {
    ull r; asm("mov.b64 %0, {%1, %2};" : "=l"(r) : "f"(lo), "f"(hi)); return r;
}
__device__ __forceinline__ float2 upk(ull v) {
    float2 r; asm("mov.b64 {%0, %1}, %2;" : "=f"(r.x), "=f"(r.y) : "l"(v)); return r;
}
__device__ __forceinline__ uint packbf(float a, float b) {
    __nv_bfloat162 h = __floats2bfloat162_rn(a, b);
    return *reinterpret_cast<uint*>(&h);
}
__device__ __forceinline__ ushort_t bfbits(float v) {
    __nv_bfloat16 b = __float2bfloat16_rn(v);
    return *reinterpret_cast<ushort_t*>(&b);
}
__device__ __forceinline__ ull b2u(uint u) {
    return pk(__uint_as_float(u << 16), __uint_as_float(u & 0xffff0000u));
}
__device__ __forceinline__ uint sptr(const void* p) {
    return (uint)__cvta_generic_to_shared(p);
}
__device__ __forceinline__ void ldsm_x4(uint &r0, uint &r1, uint &r2, uint &r3, uint addr) {
    asm volatile("ldmatrix.sync.aligned.m8n8.x4.shared.b16 {%0,%1,%2,%3}, [%4];"
                 : "=r"(r0), "=r"(r1), "=r"(r2), "=r"(r3) : "r"(addr));
}
__device__ __forceinline__ void ldsm_x2t(uint &r0, uint &r1, uint addr) {
    asm volatile("ldmatrix.sync.aligned.m8n8.x2.trans.shared.b16 {%0,%1}, [%2];"
                 : "=r"(r0), "=r"(r1) : "r"(addr));
}
__device__ __forceinline__ void mma16816(float* c, const uint* a, uint b0, uint b1) {
    asm volatile("mma.sync.aligned.m16n8k16.row.col.f32.bf16.bf16.f32 "
                 "{%0,%1,%2,%3}, {%4,%5,%6,%7}, {%8,%9}, {%0,%1,%2,%3};"
                 : "+f"(c[0]), "+f"(c[1]), "+f"(c[2]), "+f"(c[3])
                 : "r"(a[0]), "r"(a[1]), "r"(a[2]), "r"(a[3]), "r"(b0), "r"(b1));
}
__device__ __forceinline__ void stage_w4(ushort_t* dst, const float* src) {
    float4 w = *reinterpret_cast<const float4*>(src);
    uint2 u; u.x = packbf(w.x, w.y); u.y = packbf(w.z, w.w);
    *reinterpret_cast<uint2*>(dst) = u;
}

// =================================================================
// Kernel A: LN1 -> QKV MMA GEMM -> qLN/kLN -> q/k/v bf16
// (R15 version — best measured: parallel prologue, bf16 q)
// =================================================================
static constexpr int SMEM_A = 192 * 68 * 4;   // 52224 (gemm phase 36864 aliased)

__global__ void __launch_bounds__(384, 2)
kA(const float* __restrict__ x, const float* __restrict__ n1w, const float* __restrict__ n1b,
   const float* __restrict__ qkvw, const float* __restrict__ qkvb,
   const float* __restrict__ qnw, const float* __restrict__ qnb,
   const float* __restrict__ knw, const float* __restrict__ knb)
{
    extern __shared__ float sm[];
    ushort_t* wbf  = reinterpret_cast<ushort_t*>(sm);          // [192][72]
    ushort_t* actb = wbf + 192 * 72;                           // [64][72]
    float*    stage = sm;                                      // [192][68] aliased
    const int tid = threadIdx.x;
    const int p0 = blockIdx.x * 64;

    if (tid >= 256) {
        const int t2 = tid - 256;
        #pragma unroll
        for (int t = 0; t < 24; t++) {
            int idx = (t2 + t * 128) * 4;
            int o = idx >> 6, c = idx & 63;
            stage_w4(&wbf[o * 72 + c], &qkvw[idx]);
        }
    } else {
        const int s = tid & 3, px = tid >> 2;
        const int p = p0 + px;
        float xv[16];
        float sum = 0.f, sq = 0.f;
        #pragma unroll
        for (int j = 0; j < 16; j++) {
            float v = x[(s * 16 + j) * NPIX + p];
            xv[j] = v; sum += v; sq += v * v;
        }
        sum += __shfl_xor_sync(0xffffffffu, sum, 1);
        sum += __shfl_xor_sync(0xffffffffu, sum, 2);
        sq  += __shfl_xor_sync(0xffffffffu, sq, 1);
        sq  += __shfl_xor_sync(0xffffffffu, sq, 2);
        float mean = sum * (1.f / 64);
        float inv = rsqrtf(sq * (1.f / 64) - mean * mean + LNEPS);
        #pragma unroll
        for (int j = 0; j < 16; j++) {
            int c = s * 16 + j;
            actb[c * 72 + px] = bfbits((xv[j] - mean) * inv * n1w[c] + n1b[c]);
        }
    }
    __syncthreads();

    const int wid = tid >> 5, lane = tid & 31;
    const int gid = lane >> 2, tig = lane & 3;
    const int q4 = lane >> 3, r4 = lane & 7;
    const int lr = lane & 15;
    const int m0 = wid * 16;

    uint a[4][4];
    #pragma unroll
    for (int ks = 0; ks < 4; ks++) {
        int arow = m0 + r4 + ((q4 & 1) << 3);
        int acol = ks * 16 + ((q4 >> 1) << 3);
        ldsm_x4(a[ks][0], a[ks][1], a[ks][2], a[ks][3], sptr(&wbf[arow * 72 + acol]));
    }
    float c[8][4];
    #pragma unroll
    for (int nt = 0; nt < 8; nt++)
        #pragma unroll
        for (int i = 0; i < 4; i++) c[nt][i] = 0.f;
    #pragma unroll
    for (int nt = 0; nt < 8; nt++) {
        #pragma unroll
        for (int ks = 0; ks < 4; ks++) {
            uint b0, b1;
            ldsm_x2t(b0, b1, sptr(&actb[(ks * 16 + lr) * 72 + nt * 8]));
            mma16816(c[nt], a[ks], b0, b1);
        }
    }
    __syncthreads();

    #pragma unroll
    for (int nt = 0; nt < 8; nt++) {
        int col = nt * 8 + 2 * tig;
        *reinterpret_cast<float2*>(&stage[(m0 + gid) * 68 + col])     = make_float2(c[nt][0], c[nt][1]);
        *reinterpret_cast<float2*>(&stage[(m0 + 8 + gid) * 68 + col]) = make_float2(c[nt][2], c[nt][3]);
    }
    __syncthreads();

    const int grp = wid >> 2;           // 0=q, 1=k, 2=v
    const int t2 = tid & 127;
    const int s = t2 & 1, px = t2 >> 1;
    const int p = p0 + px;
    const int base = grp * 64 + s * 32;

    float vv[32];
    if (grp == 2) {
        #pragma unroll
        for (int j = 0; j < 32; j++)
            vv[j] = stage[(base + j) * 68 + px] + qkvb[base + j];
    } else {
        float sum = 0.f, sq = 0.f;
        #pragma unroll
        for (int j = 0; j < 32; j++) {
            float v = stage[(base + j) * 68 + px] + qkvb[base + j];
            vv[j] = v; sum += v; sq += v * v;
        }
        sum += __shfl_xor_sync(0xffffffffu, sum, 1);
        sq  += __shfl_xor_sync(0xffffffffu, sq, 1);
        float mean = sum * (1.f / 64);
        float inv = rsqrtf(sq * (1.f / 64) - mean * mean + LNEPS);
        if (grp == 0) {
            #pragma unroll
            for (int j = 0; j < 32; j++) {
                int ch = s * 32 + j;
                vv[j] = ((vv[j] - mean) * inv * qnw[ch] + qnb[ch]) * QSCALE;
            }
        } else {
            #pragma unroll
            for (int j = 0; j < 32; j++) {
                int ch = s * 32 + j;
                vv[j] = (vv[j] - mean) * inv * knw[ch] + knb[ch];
            }
        }
    }
    ushort_t* dst = (grp == 0) ? g_qb : (grp == 1) ? g_kb : g_vb;
    #pragma unroll
    for (int h4 = 0; h4 < 4; h4++) {
        int h8 = s * 4 + h4;
        uint4 u;
        u.x = packbf(vv[h4*8+0], vv[h4*8+1]);
        u.y = packbf(vv[h4*8+2], vv[h4*8+3]);
        u.z = packbf(vv[h4*8+4], vv[h4*8+5]);
        u.w = packbf(vv[h4*8+6], vv[h4*8+7]);
        *reinterpret_cast<uint4*>(&dst[(h8 * NPIX + p) * 8]) = u;
    }
}

// =================================================================
// Kernel B: neighborhood attention (R15 version — bf16 q)
// =================================================================
static constexpr int HS_B = 67;
static constexpr int PL_B = 44 * HS_B;
static constexpr int SMEM_B = 2 * PL_B * 16;          // 94336 B

__device__ __forceinline__ int bswz(int c) { return c ^ (((c >> 4) & 1) << 2); }

__global__ void __launch_bounds__(256, 2)
kB()
{
    extern __shared__ uint4 smu[];
    const int tile = blockIdx.x, head = blockIdx.y;
    const int th0 = (tile >> 2) * 16, tw0 = (tile & 3) * 32;
    const int tid = threadIdx.x;
    const ushort_t* kg = g_kb + head * (NPIX * 8);
    const ushort_t* vg = g_vb + head * (NPIX * 8);

    for (int e = tid; e < 2 * 44 * 60; e += 256) {
        int arr = (e >= 44 * 60) ? 1 : 0;
        int i = e - arr * (44 * 60);
        int r = i / 60, col = i - r * 60;
        int hh = min(max(th0 - 16 + r, 0), 127);
        int ww = min(max(tw0 - 16 + col, 0), 127);
        const ushort_t* src = arr ? vg : kg;
        smu[arr * PL_B + r * HS_B + bswz(col)] =
            *reinterpret_cast<const uint4*>(src + (hh * 128 + ww) * 8);
    }
    __syncthreads();

    const int quad = tid >> 1;
    const int half = tid & 1;
    const int qy   = quad >> 3;
    const int qx8  = quad & 7;
    const int wloc = (qx8 & 3) + ((qx8 >> 2) << 4);
    const int h  = th0 + qy;
    const int wb = tw0 + wloc;

    ulonglong2 qA[4], qB[4];
    #pragma unroll
    for (int t = 0; t < 4; t++) {
        uint4 qu = *reinterpret_cast<const uint4*>(&g_qb[(head * NPIX + h * 128 + wb + 4 * t) * 8]);
        qA[t].x = b2u(qu.x); qA[t].y = b2u(qu.y);
        qB[t].x = b2u(qu.z); qB[t].y = b2u(qu.w);
    }

    float l[4] = {0.f, 0.f, 0.f, 0.f};
    ull acc2[4][4];
    #pragma unroll
    for (int t = 0; t < 4; t++)
        #pragma unroll
        for (int i = 0; i < 4; i++) acc2[t][i] = 0ull;

    #pragma unroll
    for (int ah = 0; ah < 4; ah++) {
        int a = half * 4 + ah;
        int oh = 4 * a - 16;
        bool vr = (unsigned)(h + oh) < 128u;
        int rbase = (qy + 16 + oh) * HS_B;
        #pragma unroll
        for (int s = 0; s < 11; s++) {
            int off = rbase + bswz(wloc + 4 * s);
            bool ok = vr && ((unsigned)(wb + 4 * s - 16) < 128u);
            uint4 ku = smu[off];
            uint4 vu = smu[PL_B + off];
            ull kp0 = b2u(ku.x), kp1 = b2u(ku.y), kp2 = b2u(ku.z), kp3 = b2u(ku.w);
            ull vp0 = b2u(vu.x), vp1 = b2u(vu.y), vp2 = b2u(vu.z), vp3 = b2u(vu.w);
            #pragma unroll
            for (int t = 0; t < 4; t++) {
                if (t > s || t < s - 7) continue;
                ull s2 = 0ull;
                FMA2(s2, kp0, qA[t].x);
                FMA2(s2, kp1, qA[t].y);
                FMA2(s2, kp2, qB[t].x);
                FMA2(s2, kp3, qB[t].y);
                float2 sf = upk(s2);
                float sc = ok ? (sf.x + sf.y) : -1e30f;
                float ee = __expf(sc);
                l[t] += ee;
                ull e2 = pk(ee, ee);
                FMA2(acc2[t][0], vp0, e2);
                FMA2(acc2[t][1], vp1, e2);
                FMA2(acc2[t][2], vp2, e2);
                FMA2(acc2[t][3], vp3, e2);
            }
        }
    }

    #pragma unroll
    for (int t = 0; t < 4; t++) {
        float lt = l[t] + __shfl_xor_sync(0xffffffffu, l[t], 1);
        float rl = 1.0f / lt;
        int p = h * 128 + wb + 4 * t;
        #pragma unroll
        for (int i = 0; i < 4; i++) {
            float2 f = upk(acc2[t][i]);
            f.x += __shfl_xor_sync(0xffffffffu, f.x, 1);
            f.y += __shfl_xor_sync(0xffffffffu, f.y, 1);
            if (half == 0) {
                g_attb[(head * 8 + 2 * i)     * NPIX + p] = bfbits(f.x * rl);
                g_attb[(head * 8 + 2 * i + 1) * NPIX + p] = bfbits(f.y * rl);
            }
        }
    }
}

// =================================================================
// Kernel CDE: proj+LN2 -> fc1+LN+SiLU -> fc2+residual, fused.
// (R13-exact: upfront vectorized staging, x1 via gmem, 96KB smem)
// =================================================================
static constexpr int OFF_W1  = 0;
static constexpr int OFF_W2  = 9216;
static constexpr int OFF_W3  = 27648;
static constexpr int OFF_ACT = 45056;
static constexpr int OFF_STG = 63488;
static constexpr int SMEM_F  = 98304;             // 96 KB

__global__ void __launch_bounds__(256, 2)
kCDE(const float* __restrict__ x,
     const float* __restrict__ projw, const float* __restrict__ projb,
     const float* __restrict__ g1, const float* __restrict__ n2w, const float* __restrict__ n2b,
     const float* __restrict__ fc1w, const float* __restrict__ fc1b,
     const float* __restrict__ mnw, const float* __restrict__ mnb,
     const float* __restrict__ fc2w, const float* __restrict__ fc2b,
     const float* __restrict__ g2, float* __restrict__ out)
{
    extern __shared__ char smc[];
    ushort_t* w1  = reinterpret_cast<ushort_t*>(smc + OFF_W1);
    ushort_t* w2  = reinterpret_cast<ushort_t*>(smc + OFF_W2);
    ushort_t* w3  = reinterpret_cast<ushort_t*>(smc + OFF_W3);
    ushort_t* act = reinterpret_cast<ushort_t*>(smc + OFF_ACT);
    float*    stg = reinterpret_cast<float*>(smc + OFF_STG);
    const int tid = threadIdx.x;
    const int p0 = blockIdx.x * 64;

    #pragma unroll
    for (int t = 0; t < 4; t++) {
        int idx = (tid + t * 256) * 4;
        int o = idx >> 6, c = idx & 63;
        stage_w4(&w1[o * 72 + c], &projw[idx]);
    }
    #pragma unroll
    for (int t = 0; t < 8; t++) {
        int idx = (tid + t * 256) * 4;
        int o = idx >> 6, c = idx & 63;
        stage_w4(&w2[o * 72 + c], &fc1w[idx]);
    }
    #pragma unroll
    for (int t = 0; t < 8; t++) {
        int idx = (tid + t * 256) * 4;
        int o = idx >> 7, c = idx & 127;
        stage_w4(&w3[o * 136 + c], &fc2w[idx]);
    }
    #pragma unroll
    for (int t = 0; t < 2; t++) {
        int i = tid + t * 256;
        int c = i >> 3, u = i & 7;
        *reinterpret_cast<uint4*>(&act[c * 72 + u * 8]) =
            *reinterpret_cast<const uint4*>(&g_attb[c * NPIX + p0 + u * 8]);
    }
    __syncthreads();

    const int wid = tid >> 5, lane = tid & 31;
    const int gid = lane >> 2, tig = lane & 3;
    const int q4 = lane >> 3, r4 = lane & 7;
    const int lr = lane & 15;

    // ================= GEMM1: proj =================
    {
        const int ot = wid & 3, nh = wid >> 2;
        const int m0 = ot * 16;
        uint a[4][4];
        #pragma unroll
        for (int ks = 0; ks < 4; ks++) {
            int arow = m0 + r4 + ((q4 & 1) << 3);
            int acol = ks * 16 + ((q4 >> 1) << 3);
            ldsm_x4(a[ks][0], a[ks][1], a[ks][2], a[ks][3], sptr(&w1[arow * 72 + acol]));
        }
        float c[4][4];
        #pragma unroll
        for (int nt = 0; nt < 4; nt++)
            #pragma unroll
            for (int i = 0; i < 4; i++) c[nt][i] = 0.f;
        #pragma unroll
        for (int nt = 0; nt < 4; nt++) {
            int ntg = nh * 4 + nt;
            #pragma unroll
            for (int ks = 0; ks < 4; ks++) {
                uint b0, b1;
                ldsm_x2t(b0, b1, sptr(&act[(ks * 16 + lr) * 72 + ntg * 8]));
                mma16816(c[nt], a[ks], b0, b1);
            }
        }
        __syncthreads();
        #pragma unroll
        for (int nt = 0; nt < 4; nt++) {
            int col = (nh * 4 + nt) * 8 + 2 * tig;
            *reinterpret_cast<float2*>(&stg[(m0 + gid) * 68 + col])     = make_float2(c[nt][0], c[nt][1]);
            *reinterpret_cast<float2*>(&stg[(m0 + 8 + gid) * 68 + col]) = make_float2(c[nt][2], c[nt][3]);
        }
        __syncthreads();
    }

    // ============ Epilogue1: x1 + LN2 ============
    {
        const int s = tid & 3, px = tid >> 2;
        const int p = p0 + px;
        float vv[16];
        float sum = 0.f, sq = 0.f;
        #pragma unroll
        for (int j = 0; j < 16; j++) {
            int ch = s * 16 + j;
            float v = x[ch * NPIX + p] + g1[ch] * (stg[ch * 68 + px] + projb[ch]);
            g_x1[ch * NPIX + p] = v;
            vv[j] = v; sum += v; sq += v * v;
        }
        sum += __shfl_xor_sync(0xffffffffu, sum, 1);
        sum += __shfl_xor_sync(0xffffffffu, sum, 2);
        sq  += __shfl_xor_sync(0xffffffffu, sq, 1);
        sq  += __shfl_xor_sync(0xffffffffu, sq, 2);
        float mean = sum * (1.f / 64);
        float inv = rsqrtf(sq * (1.f / 64) - mean * mean + LNEPS);
        #pragma unroll
        for (int j = 0; j < 16; j++) {
            int ch = s * 16 + j;
            act[ch * 72 + px] = bfbits((vv[j] - mean) * inv * n2w[ch] + n2b[ch]);
        }
        __syncthreads();
    }

    // ================= GEMM2: fc1 =================
    {
        const int m0 = wid * 16;
        uint a[4][4];
        #pragma unroll
        for (int ks = 0; ks < 4; ks++) {
            int arow = m0 + r4 + ((q4 & 1) << 3);
            int acol = ks * 16 + ((q4 >> 1) << 3);
            ldsm_x4(a[ks][0], a[ks][1], a[ks][2], a[ks][3], sptr(&w2[arow * 72 + acol]));
        }
        float c[8][4];
        #pragma unroll
        for (int nt = 0; nt < 8; nt++)
            #pragma unroll
            for (int i = 0; i < 4; i++) c[nt][i] = 0.f;
        #pragma unroll
        for (int nt = 0; nt < 8; nt++) {
            #pragma unroll
            for (int ks = 0; ks < 4; ks++) {
                uint b0, b1;
                ldsm_x2t(b0, b1, sptr(&act[(ks * 16 + lr) * 72 + nt * 8]));
                mma16816(c[nt], a[ks], b0, b1);
            }
        }
        __syncthreads();
        #pragma unroll
        for (int nt = 0; nt < 8; nt++) {
            int col = nt * 8 + 2 * tig;
            *reinterpret_cast<float2*>(&stg[(m0 + gid) * 68 + col])     = make_float2(c[nt][0], c[nt][1]);
            *reinterpret_cast<float2*>(&stg[(m0 + 8 + gid) * 68 + col]) = make_float2(c[nt][2], c[nt][3]);
        }
        __syncthreads();
    }

    // ============ Epilogue2: LN(128) + SiLU ============
    {
        const int s = tid & 3, px = tid >> 2;
        float vv[32];
        float sum = 0.f, sq = 0.f;
        #pragma unroll
        for (int j = 0; j < 32; j++) {
            int ch = s * 32 + j;
            float v = stg[ch * 68 + px] + fc1b[ch];
            vv[j] = v; sum += v; sq += v * v;
        }
        sum += __shfl_xor_sync(0xffffffffu, sum, 1);
        sum += __shfl_xor_sync(0xffffffffu, sum, 2);
        sq  += __shfl_xor_sync(0xffffffffu, sq, 1);
        sq  += __shfl_xor_sync(0xffffffffu, sq, 2);
        float mean = sum * (1.f / 128);
        float inv = rsqrtf(sq * (1.f / 128) - mean * mean + LNEPS);
        #pragma unroll
        for (int j = 0; j < 32; j++) {
            int ch = s * 32 + j;
            float hh = (vv[j] - mean) * inv * mnw[ch] + mnb[ch];
            act[ch * 72 + px] = bfbits(hh / (1.f + __expf(-hh)));
        }
        __syncthreads();
    }

    // ======== GEMM3: fc2 + residual epilogue ========
    {
        const int ot = wid & 3, nh = wid >> 2;
        const int m0 = ot * 16;
        uint a[8][4];
        #pragma unroll
        for (int ks = 0; ks < 8; ks++) {
            int arow = m0 + r4 + ((q4 & 1) << 3);
            int acol = ks * 16 + ((q4 >> 1) << 3);
            ldsm_x4(a[ks][0], a[ks][1], a[ks][2], a[ks][3], sptr(&w3[arow * 136 + acol]));
        }
        float c[4][4];
        #pragma unroll
        for (int nt = 0; nt < 4; nt++)
            #pragma unroll
            for (int i = 0; i < 4; i++) c[nt][i] = 0.f;
        #pragma unroll
        for (int nt = 0; nt < 4; nt++) {
            int ntg = nh * 4 + nt;
            #pragma unroll
            for (int ks = 0; ks < 8; ks++) {
                uint b0, b1;
                ldsm_x2t(b0, b1, sptr(&act[(ks * 16 + lr) * 72 + ntg * 8]));
                mma16816(c[nt], a[ks], b0, b1);
            }
        }
        const int ch0 = m0 + gid, ch1 = ch0 + 8;
        const float fb0 = fc2b[ch0], gg0 = g2[ch0];
        const float fb1 = fc2b[ch1], gg1 = g2[ch1];
        #pragma unroll
        for (int nt = 0; nt < 4; nt++) {
            int p = p0 + (nh * 4 + nt) * 8 + 2 * tig;
            float2 x0 = *reinterpret_cast<const float2*>(&g_x1[ch0 * NPIX + p]);
            float2 x1 = *reinterpret_cast<const float2*>(&g_x1[ch1 * NPIX + p]);
            float2 o0 = make_float2(x0.x + gg0 * (c[nt][0] + fb0), x0.y + gg0 * (c[nt][1] + fb0));
            float2 o1 = make_float2(x1.x + gg1 * (c[nt][2] + fb1), x1.y + gg1 * (c[nt][3] + fb1));
            *reinterpret_cast<float2*>(&out[ch0 * NPIX + p]) = o0;
            *reinterpret_cast<float2*>(&out[ch1 * NPIX + p]) = o1;
        }
    }
}

// =================================================================
extern "C" void kernel_launch(void* const* d_in, const int* in_sizes, int n_in,
                              void* d_out, int out_size)
{
    const float* x     = (const float*)d_in[0];
    const float* n1w   = (const float*)d_in[1];
    const float* n1b   = (const float*)d_in[2];
    const float* qkvw  = (const float*)d_in[3];
    const float* qkvb  = (const float*)d_in[4];
    const float* qnw   = (const float*)d_in[5];
    const float* qnb   = (const float*)d_in[6];
    const float* knw   = (const float*)d_in[7];
    const float* knb   = (const float*)d_in[8];
    const float* projw = (const float*)d_in[9];
    const float* projb = (const float*)d_in[10];
    const float* g1    = (const float*)d_in[11];
    const float* n2w   = (const float*)d_in[12];
    const float* n2b   = (const float*)d_in[13];
    const float* fc1w  = (const float*)d_in[14];
    const float* fc1b  = (const float*)d_in[15];
    const float* mnw   = (const float*)d_in[16];
    const float* mnb   = (const float*)d_in[17];
    const float* fc2w  = (const float*)d_in[18];
    const float* fc2b  = (const float*)d_in[19];
    const float* g2    = (const float*)d_in[20];
    float* out = (float*)d_out;

    cudaFuncSetAttribute(kA,   cudaFuncAttributeMaxDynamicSharedMemorySize, SMEM_A);
    cudaFuncSetAttribute(kB,   cudaFuncAttributeMaxDynamicSharedMemorySize, SMEM_B);
    cudaFuncSetAttribute(kCDE, cudaFuncAttributeMaxDynamicSharedMemorySize, SMEM_F);

    kA<<<256, 384, SMEM_A>>>(x, n1w, n1b, qkvw, qkvb, qnw, qnb, knw, knb);
    kB<<<dim3(32, 8), 256, SMEM_B>>>();
    kCDE<<<256, 256, SMEM_F>>>(x, projw, projb, g1, n2w, n2b,
                               fc1w, fc1b, mnw, mnb, fc2w, fc2b, g2, out);
}

// round 17
// speedup vs baseline: 1.0463x; 1.0007x over previous
#include <cuda_runtime.h>
#include <cuda_bf16.h>

typedef unsigned long long ull;
typedef unsigned int uint;
typedef unsigned short ushort_t;

static constexpr int IMG   = 128;
static constexpr int NPIX  = IMG * IMG;      // 16384
static constexpr int CH    = 64;
static constexpr int NHEAD = 8;
static constexpr int HIDN  = 128;
static constexpr float LNEPS  = 1e-5f;
static constexpr float QSCALE = 0.35355339059327373f;   // 8^-0.5

// ---------------- scratch ----------------
__device__ __align__(16) ushort_t g_qb [NHEAD * NPIX * 8];   // bf16
__device__ __align__(16) ushort_t g_kb [NHEAD * NPIX * 8];   // bf16
__device__ __align__(16) ushort_t g_vb [NHEAD * NPIX * 8];   // bf16
__device__ __align__(16) ushort_t g_attb[CH * NPIX];         // bf16
__device__ __align__(16) float    g_x1 [CH * NPIX];

// ---------------- helpers ----------------
#define FMA2(acc, a, b) asm("fma.rn.f32x2 %0, %1, %2, %0;" : "+l"(acc) : "l"(a), "l"(b))

__device__ __forceinline__ ull pk(float lo, float hi) {
    ull r; asm("mov.b64 %0, {%1, %2};" : "=l"(r) : "f"(lo), "f"(hi)); return r;
}
__device__ __forceinline__ float2 upk(ull v) {
    float2 r; asm("mov.b64 {%0, %1}, %2;" : "=f"(r.x), "=f"(r.y) : "l"(v)); return r;
}
__device__ __forceinline__ uint packbf(float a, float b) {
    __nv_bfloat162 h = __floats2bfloat162_rn(a, b);
    return *reinterpret_cast<uint*>(&h);
}
__device__ __forceinline__ ushort_t bfbits(float v) {
    __nv_bfloat16 b = __float2bfloat16_rn(v);
    return *reinterpret_cast<ushort_t*>(&b);
}
__device__ __forceinline__ ull b2u(uint u) {
    return pk(__uint_as_float(u << 16), __uint_as_float(u & 0xffff0000u));
}
__device__ __forceinline__ uint sptr(const void* p) {
    return (uint)__cvta_generic_to_shared(p);
}
__device__ __forceinline__ void ldsm_x4(uint &r0, uint &r1, uint &r2, uint &r3, uint addr) {
    asm volatile("ldmatrix.sync.aligned.m8n8.x4.shared.b16 {%0,%1,%2,%3}, [%4];"
                 : "=r"(r0), "=r"(r1), "=r"(r2), "=r"(r3) : "r"(addr));
}
__device__ __forceinline__ void ldsm_x2t(uint &r0, uint &r1, uint addr) {
    asm volatile("ldmatrix.sync.aligned.m8n8.x2.trans.shared.b16 {%0,%1}, [%2];"
                 : "=r"(r0), "=r"(r1) : "r"(addr));
}
__device__ __forceinline__ void mma16816(float* c, const uint* a, uint b0, uint b1) {
    asm volatile("mma.sync.aligned.m16n8k16.row.col.f32.bf16.bf16.f32 "
                 "{%0,%1,%2,%3}, {%4,%5,%6,%7}, {%8,%9}, {%0,%1,%2,%3};"
                 : "+f"(c[0]), "+f"(c[1]), "+f"(c[2]), "+f"(c[3])
                 : "r"(a[0]), "r"(a[1]), "r"(a[2]), "r"(a[3]), "r"(b0), "r"(b1));
}
__device__ __forceinline__ void stage_w4(ushort_t* dst, const float* src) {
    float4 w = *reinterpret_cast<const float4*>(src);
    uint2 u; u.x = packbf(w.x, w.y); u.y = packbf(w.z, w.w);
    *reinterpret_cast<uint2*>(dst) = u;
}

// =================================================================
// Kernel A: LN1 -> QKV MMA GEMM -> qLN/kLN -> q/k/v bf16
// =================================================================
static constexpr int SMEM_A = 192 * 68 * 4;   // 52224

__global__ void __launch_bounds__(384, 2)
kA(const float* __restrict__ x, const float* __restrict__ n1w, const float* __restrict__ n1b,
   const float* __restrict__ qkvw, const float* __restrict__ qkvb,
   const float* __restrict__ qnw, const float* __restrict__ qnb,
   const float* __restrict__ knw, const float* __restrict__ knb)
{
    extern __shared__ float sm[];
    ushort_t* wbf  = reinterpret_cast<ushort_t*>(sm);          // [192][72]
    ushort_t* actb = wbf + 192 * 72;                           // [64][72]
    float*    stage = sm;                                      // [192][68] aliased
    const int tid = threadIdx.x;
    const int p0 = blockIdx.x * 64;

    if (tid >= 256) {
        const int t2 = tid - 256;
        #pragma unroll
        for (int t = 0; t < 24; t++) {
            int idx = (t2 + t * 128) * 4;
            int o = idx >> 6, c = idx & 63;
            stage_w4(&wbf[o * 72 + c], &qkvw[idx]);
        }
    } else {
        const int s = tid & 3, px = tid >> 2;
        const int p = p0 + px;
        float xv[16];
        float sum = 0.f, sq = 0.f;
        #pragma unroll
        for (int j = 0; j < 16; j++) {
            float v = x[(s * 16 + j) * NPIX + p];
            xv[j] = v; sum += v; sq += v * v;
        }
        sum += __shfl_xor_sync(0xffffffffu, sum, 1);
        sum += __shfl_xor_sync(0xffffffffu, sum, 2);
        sq  += __shfl_xor_sync(0xffffffffu, sq, 1);
        sq  += __shfl_xor_sync(0xffffffffu, sq, 2);
        float mean = sum * (1.f / 64);
        float inv = rsqrtf(sq * (1.f / 64) - mean * mean + LNEPS);
        #pragma unroll
        for (int j = 0; j < 16; j++) {
            int c = s * 16 + j;
            actb[c * 72 + px] = bfbits((xv[j] - mean) * inv * n1w[c] + n1b[c]);
        }
    }
    __syncthreads();

    const int wid = tid >> 5, lane = tid & 31;
    const int gid = lane >> 2, tig = lane & 3;
    const int q4 = lane >> 3, r4 = lane & 7;
    const int lr = lane & 15;
    const int m0 = wid * 16;

    uint a[4][4];
    #pragma unroll
    for (int ks = 0; ks < 4; ks++) {
        int arow = m0 + r4 + ((q4 & 1) << 3);
        int acol = ks * 16 + ((q4 >> 1) << 3);
        ldsm_x4(a[ks][0], a[ks][1], a[ks][2], a[ks][3], sptr(&wbf[arow * 72 + acol]));
    }
    float c[8][4];
    #pragma unroll
    for (int nt = 0; nt < 8; nt++)
        #pragma unroll
        for (int i = 0; i < 4; i++) c[nt][i] = 0.f;
    #pragma unroll
    for (int nt = 0; nt < 8; nt++) {
        #pragma unroll
        for (int ks = 0; ks < 4; ks++) {
            uint b0, b1;
            ldsm_x2t(b0, b1, sptr(&actb[(ks * 16 + lr) * 72 + nt * 8]));
            mma16816(c[nt], a[ks], b0, b1);
        }
    }
    __syncthreads();

    #pragma unroll
    for (int nt = 0; nt < 8; nt++) {
        int col = nt * 8 + 2 * tig;
        *reinterpret_cast<float2*>(&stage[(m0 + gid) * 68 + col])     = make_float2(c[nt][0], c[nt][1]);
        *reinterpret_cast<float2*>(&stage[(m0 + 8 + gid) * 68 + col]) = make_float2(c[nt][2], c[nt][3]);
    }
    __syncthreads();

    const int grp = wid >> 2;           // 0=q, 1=k, 2=v
    const int t2 = tid & 127;
    const int s = t2 & 1, px = t2 >> 1;
    const int p = p0 + px;
    const int base = grp * 64 + s * 32;

    float vv[32];
    if (grp == 2) {
        #pragma unroll
        for (int j = 0; j < 32; j++)
            vv[j] = stage[(base + j) * 68 + px] + qkvb[base + j];
    } else {
        float sum = 0.f, sq = 0.f;
        #pragma unroll
        for (int j = 0; j < 32; j++) {
            float v = stage[(base + j) * 68 + px] + qkvb[base + j];
            vv[j] = v; sum += v; sq += v * v;
        }
        sum += __shfl_xor_sync(0xffffffffu, sum, 1);
        sq  += __shfl_xor_sync(0xffffffffu, sq, 1);
        float mean = sum * (1.f / 64);
        float inv = rsqrtf(sq * (1.f / 64) - mean * mean + LNEPS);
        if (grp == 0) {
            #pragma unroll
            for (int j = 0; j < 32; j++) {
                int ch = s * 32 + j;
                vv[j] = ((vv[j] - mean) * inv * qnw[ch] + qnb[ch]) * QSCALE;
            }
        } else {
            #pragma unroll
            for (int j = 0; j < 32; j++) {
                int ch = s * 32 + j;
                vv[j] = (vv[j] - mean) * inv * knw[ch] + knb[ch];
            }
        }
    }
    ushort_t* dst = (grp == 0) ? g_qb : (grp == 1) ? g_kb : g_vb;
    #pragma unroll
    for (int h4 = 0; h4 < 4; h4++) {
        int h8 = s * 4 + h4;
        uint4 u;
        u.x = packbf(vv[h4*8+0], vv[h4*8+1]);
        u.y = packbf(vv[h4*8+2], vv[h4*8+3]);
        u.z = packbf(vv[h4*8+4], vv[h4*8+5]);
        u.w = packbf(vv[h4*8+6], vv[h4*8+7]);
        *reinterpret_cast<uint4*>(&dst[(h8 * NPIX + p) * 8]) = u;
    }
}

// =================================================================
// Kernel B: neighborhood attention (unchanged from R16)
// =================================================================
static constexpr int HS_B = 67;
static constexpr int PL_B = 44 * HS_B;
static constexpr int SMEM_B = 2 * PL_B * 16;          // 94336 B

__device__ __forceinline__ int bswz(int c) { return c ^ (((c >> 4) & 1) << 2); }

__global__ void __launch_bounds__(256, 2)
kB()
{
    extern __shared__ uint4 smu[];
    const int tile = blockIdx.x, head = blockIdx.y;
    const int th0 = (tile >> 2) * 16, tw0 = (tile & 3) * 32;
    const int tid = threadIdx.x;
    const ushort_t* kg = g_kb + head * (NPIX * 8);
    const ushort_t* vg = g_vb + head * (NPIX * 8);

    for (int e = tid; e < 2 * 44 * 60; e += 256) {
        int arr = (e >= 44 * 60) ? 1 : 0;
        int i = e - arr * (44 * 60);
        int r = i / 60, col = i - r * 60;
        int hh = min(max(th0 - 16 + r, 0), 127);
        int ww = min(max(tw0 - 16 + col, 0), 127);
        const ushort_t* src = arr ? vg : kg;
        smu[arr * PL_B + r * HS_B + bswz(col)] =
            *reinterpret_cast<const uint4*>(src + (hh * 128 + ww) * 8);
    }
    __syncthreads();

    const int quad = tid >> 1;
    const int half = tid & 1;
    const int qy   = quad >> 3;
    const int qx8  = quad & 7;
    const int wloc = (qx8 & 3) + ((qx8 >> 2) << 4);
    const int h  = th0 + qy;
    const int wb = tw0 + wloc;

    ulonglong2 qA[4], qB[4];
    #pragma unroll
    for (int t = 0; t < 4; t++) {
        uint4 qu = *reinterpret_cast<const uint4*>(&g_qb[(head * NPIX + h * 128 + wb + 4 * t) * 8]);
        qA[t].x = b2u(qu.x); qA[t].y = b2u(qu.y);
        qB[t].x = b2u(qu.z); qB[t].y = b2u(qu.w);
    }

    float l[4] = {0.f, 0.f, 0.f, 0.f};
    ull acc2[4][4];
    #pragma unroll
    for (int t = 0; t < 4; t++)
        #pragma unroll
        for (int i = 0; i < 4; i++) acc2[t][i] = 0ull;

    #pragma unroll
    for (int ah = 0; ah < 4; ah++) {
        int a = half * 4 + ah;
        int oh = 4 * a - 16;
        bool vr = (unsigned)(h + oh) < 128u;
        int rbase = (qy + 16 + oh) * HS_B;
        #pragma unroll
        for (int s = 0; s < 11; s++) {
            int off = rbase + bswz(wloc + 4 * s);
            bool ok = vr && ((unsigned)(wb + 4 * s - 16) < 128u);
            uint4 ku = smu[off];
            uint4 vu = smu[PL_B + off];
            ull kp0 = b2u(ku.x), kp1 = b2u(ku.y), kp2 = b2u(ku.z), kp3 = b2u(ku.w);
            ull vp0 = b2u(vu.x), vp1 = b2u(vu.y), vp2 = b2u(vu.z), vp3 = b2u(vu.w);
            #pragma unroll
            for (int t = 0; t < 4; t++) {
                if (t > s || t < s - 7) continue;
                ull s2 = 0ull;
                FMA2(s2, kp0, qA[t].x);
                FMA2(s2, kp1, qA[t].y);
                FMA2(s2, kp2, qB[t].x);
                FMA2(s2, kp3, qB[t].y);
                float2 sf = upk(s2);
                float sc = ok ? (sf.x + sf.y) : -1e30f;
                float ee = __expf(sc);
                l[t] += ee;
                ull e2 = pk(ee, ee);
                FMA2(acc2[t][0], vp0, e2);
                FMA2(acc2[t][1], vp1, e2);
                FMA2(acc2[t][2], vp2, e2);
                FMA2(acc2[t][3], vp3, e2);
            }
        }
    }

    #pragma unroll
    for (int t = 0; t < 4; t++) {
        float lt = l[t] + __shfl_xor_sync(0xffffffffu, l[t], 1);
        float rl = 1.0f / lt;
        int p = h * 128 + wb + 4 * t;
        #pragma unroll
        for (int i = 0; i < 4; i++) {
            float2 f = upk(acc2[t][i]);
            f.x += __shfl_xor_sync(0xffffffffu, f.x, 1);
            f.y += __shfl_xor_sync(0xffffffffu, f.y, 1);
            if (half == 0) {
                g_attb[(head * 8 + 2 * i)     * NPIX + p] = bfbits(f.x * rl);
                g_attb[(head * 8 + 2 * i + 1) * NPIX + p] = bfbits(f.y * rl);
            }
        }
    }
}

// =================================================================
// Kernel CDE: proj+LN2 -> fc1+LN+SiLU -> fc2+residual, fused.
// R16 + PDL: stage weights BEFORE grid-dependency sync (overlaps kB tail)
// =================================================================
static constexpr int OFF_W1  = 0;
static constexpr int OFF_W2  = 9216;
static constexpr int OFF_W3  = 27648;
static constexpr int OFF_ACT = 45056;
static constexpr int OFF_STG = 63488;
static constexpr int SMEM_F  = 98304;             // 96 KB

__global__ void __launch_bounds__(256, 2)
kCDE(const float* __restrict__ x,
     const float* __restrict__ projw, const float* __restrict__ projb,
     const float* __restrict__ g1, const float* __restrict__ n2w, const float* __restrict__ n2b,
     const float* __restrict__ fc1w, const float* __restrict__ fc1b,
     const float* __restrict__ mnw, const float* __restrict__ mnb,
     const float* __restrict__ fc2w, const float* __restrict__ fc2b,
     const float* __restrict__ g2, float* __restrict__ out)
{
    extern __shared__ char smc[];
    ushort_t* w1  = reinterpret_cast<ushort_t*>(smc + OFF_W1);
    ushort_t* w2  = reinterpret_cast<ushort_t*>(smc + OFF_W2);
    ushort_t* w3  = reinterpret_cast<ushort_t*>(smc + OFF_W3);
    ushort_t* act = reinterpret_cast<ushort_t*>(smc + OFF_ACT);
    float*    stg = reinterpret_cast<float*>(smc + OFF_STG);
    const int tid = threadIdx.x;
    const int p0 = blockIdx.x * 64;

    // ---- weight staging: independent of kB's output; runs under PDL overlap
    #pragma unroll
    for (int t = 0; t < 4; t++) {
        int idx = (tid + t * 256) * 4;
        int o = idx >> 6, c = idx & 63;
        stage_w4(&w1[o * 72 + c], &projw[idx]);
    }
    #pragma unroll
    for (int t = 0; t < 8; t++) {
        int idx = (tid + t * 256) * 4;
        int o = idx >> 6, c = idx & 63;
        stage_w4(&w2[o * 72 + c], &fc1w[idx]);
    }
    #pragma unroll
    for (int t = 0; t < 8; t++) {
        int idx = (tid + t * 256) * 4;
        int o = idx >> 7, c = idx & 127;
        stage_w4(&w3[o * 136 + c], &fc2w[idx]);
    }

    // ---- wait for kB to complete before touching g_attb
    cudaGridDependencySynchronize();

    #pragma unroll
    for (int t = 0; t < 2; t++) {
        int i = tid + t * 256;
        int c = i >> 3, u = i & 7;
        *reinterpret_cast<uint4*>(&act[c * 72 + u * 8]) =
            *reinterpret_cast<const uint4*>(&g_attb[c * NPIX + p0 + u * 8]);
    }
    __syncthreads();

    const int wid = tid >> 5, lane = tid & 31;
    const int gid = lane >> 2, tig = lane & 3;
    const int q4 = lane >> 3, r4 = lane & 7;
    const int lr = lane & 15;

    // ================= GEMM1: proj =================
    {
        const int ot = wid & 3, nh = wid >> 2;
        const int m0 = ot * 16;
        uint a[4][4];
        #pragma unroll
        for (int ks = 0; ks < 4; ks++) {
            int arow = m0 + r4 + ((q4 & 1) << 3);
            int acol = ks * 16 + ((q4 >> 1) << 3);
            ldsm_x4(a[ks][0], a[ks][1], a[ks][2], a[ks][3], sptr(&w1[arow * 72 + acol]));
        }
        float c[4][4];
        #pragma unroll
        for (int nt = 0; nt < 4; nt++)
            #pragma unroll
            for (int i = 0; i < 4; i++) c[nt][i] = 0.f;
        #pragma unroll
        for (int nt = 0; nt < 4; nt++) {
            int ntg = nh * 4 + nt;
            #pragma unroll
            for (int ks = 0; ks < 4; ks++) {
                uint b0, b1;
                ldsm_x2t(b0, b1, sptr(&act[(ks * 16 + lr) * 72 + ntg * 8]));
                mma16816(c[nt], a[ks], b0, b1);
            }
        }
        __syncthreads();
        #pragma unroll
        for (int nt = 0; nt < 4; nt++) {
            int col = (nh * 4 + nt) * 8 + 2 * tig;
            *reinterpret_cast<float2*>(&stg[(m0 + gid) * 68 + col])     = make_float2(c[nt][0], c[nt][1]);
            *reinterpret_cast<float2*>(&stg[(m0 + 8 + gid) * 68 + col]) = make_float2(c[nt][2], c[nt][3]);
        }
        __syncthreads();
    }

    // ============ Epilogue1: x1 + LN2 ============
    {
        const int s = tid & 3, px = tid >> 2;
        const int p = p0 + px;
        float vv[16];
        float sum = 0.f, sq = 0.f;
        #pragma unroll
        for (int j = 0; j < 16; j++) {
            int ch = s * 16 + j;
            float v = x[ch * NPIX + p] + g1[ch] * (stg[ch * 68 + px] + projb[ch]);
            g_x1[ch * NPIX + p] = v;
            vv[j] = v; sum += v; sq += v * v;
        }
        sum += __shfl_xor_sync(0xffffffffu, sum, 1);
        sum += __shfl_xor_sync(0xffffffffu, sum, 2);
        sq  += __shfl_xor_sync(0xffffffffu, sq, 1);
        sq  += __shfl_xor_sync(0xffffffffu, sq, 2);
        float mean = sum * (1.f / 64);
        float inv = rsqrtf(sq * (1.f / 64) - mean * mean + LNEPS);
        #pragma unroll
        for (int j = 0; j < 16; j++) {
            int ch = s * 16 + j;
            act[ch * 72 + px] = bfbits((vv[j] - mean) * inv * n2w[ch] + n2b[ch]);
        }
        __syncthreads();
    }

    // ================= GEMM2: fc1 =================
    {
        const int m0 = wid * 16;
        uint a[4][4];
        #pragma unroll
        for (int ks = 0; ks < 4; ks++) {
            int arow = m0 + r4 + ((q4 & 1) << 3);
            int acol = ks * 16 + ((q4 >> 1) << 3);
            ldsm_x4(a[ks][0], a[ks][1], a[ks][2], a[ks][3], sptr(&w2[arow * 72 + acol]));
        }
        float c[8][4];
        #pragma unroll
        for (int nt = 0; nt < 8; nt++)
            #pragma unroll
            for (int i = 0; i < 4; i++) c[nt][i] = 0.f;
        #pragma unroll
        for (int nt = 0; nt < 8; nt++) {
            #pragma unroll
            for (int ks = 0; ks < 4; ks++) {
                uint b0, b1;
                ldsm_x2t(b0, b1, sptr(&act[(ks * 16 + lr) * 72 + nt * 8]));
                mma16816(c[nt], a[ks], b0, b1);
            }
        }
        __syncthreads();
        #pragma unroll
        for (int nt = 0; nt < 8; nt++) {
            int col = nt * 8 + 2 * tig;
            *reinterpret_cast<float2*>(&stg[(m0 + gid) * 68 + col])     = make_float2(c[nt][0], c[nt][1]);
            *reinterpret_cast<float2*>(&stg[(m0 + 8 + gid) * 68 + col]) = make_float2(c[nt][2], c[nt][3]);
        }
        __syncthreads();
    }

    // ============ Epilogue2: LN(128) + SiLU ============
    {
        const int s = tid & 3, px = tid >> 2;
        float vv[32];
        float sum = 0.f, sq = 0.f;
        #pragma unroll
        for (int j = 0; j < 32; j++) {
            int ch = s * 32 + j;
            float v = stg[ch * 68 + px] + fc1b[ch];
            vv[j] = v; sum += v; sq += v * v;
        }
        sum += __shfl_xor_sync(0xffffffffu, sum, 1);
        sum += __shfl_xor_sync(0xffffffffu, sum, 2);
        sq  += __shfl_xor_sync(0xffffffffu, sq, 1);
        sq  += __shfl_xor_sync(0xffffffffu, sq, 2);
        float mean = sum * (1.f / 128);
        float inv = rsqrtf(sq * (1.f / 128) - mean * mean + LNEPS);
        #pragma unroll
        for (int j = 0; j < 32; j++) {
            int ch = s * 32 + j;
            float hh = (vv[j] - mean) * inv * mnw[ch] + mnb[ch];
            act[ch * 72 + px] = bfbits(hh / (1.f + __expf(-hh)));
        }
        __syncthreads();
    }

    // ======== GEMM3: fc2 + residual epilogue ========
    {
        const int ot = wid & 3, nh = wid >> 2;
        const int m0 = ot * 16;
        uint a[8][4];
        #pragma unroll
        for (int ks = 0; ks < 8; ks++) {
            int arow = m0 + r4 + ((q4 & 1) << 3);
            int acol = ks * 16 + ((q4 >> 1) << 3);
            ldsm_x4(a[ks][0], a[ks][1], a[ks][2], a[ks][3], sptr(&w3[arow * 136 + acol]));
        }
        float c[4][4];
        #pragma unroll
        for (int nt = 0; nt < 4; nt++)
            #pragma unroll
            for (int i = 0; i < 4; i++) c[nt][i] = 0.f;
        #pragma unroll
        for (int nt = 0; nt < 4; nt++) {
            int ntg = nh * 4 + nt;
            #pragma unroll
            for (int ks = 0; ks < 8; ks++) {
                uint b0, b1;
                ldsm_x2t(b0, b1, sptr(&act[(ks * 16 + lr) * 72 + ntg * 8]));
                mma16816(c[nt], a[ks], b0, b1);
            }
        }
        const int ch0 = m0 + gid, ch1 = ch0 + 8;
        const float fb0 = fc2b[ch0], gg0 = g2[ch0];
        const float fb1 = fc2b[ch1], gg1 = g2[ch1];
        #pragma unroll
        for (int nt = 0; nt < 4; nt++) {
            int p = p0 + (nh * 4 + nt) * 8 + 2 * tig;
            float2 x0 = *reinterpret_cast<const float2*>(&g_x1[ch0 * NPIX + p]);
            float2 x1 = *reinterpret_cast<const float2*>(&g_x1[ch1 * NPIX + p]);
            float2 o0 = make_float2(x0.x + gg0 * (c[nt][0] + fb0), x0.y + gg0 * (c[nt][1] + fb0));
            float2 o1 = make_float2(x1.x + gg1 * (c[nt][2] + fb1), x1.y + gg1 * (c[nt][3] + fb1));
            *reinterpret_cast<float2*>(&out[ch0 * NPIX + p]) = o0;
            *reinterpret_cast<float2*>(&out[ch1 * NPIX + p]) = o1;
        }
    }
}

// =================================================================
extern "C" void kernel_launch(void* const* d_in, const int* in_sizes, int n_in,
                              void* d_out, int out_size)
{
    const float* x     = (const float*)d_in[0];
    const float* n1w   = (const float*)d_in[1];
    const float* n1b   = (const float*)d_in[2];
    const float* qkvw  = (const float*)d_in[3];
    const float* qkvb  = (const float*)d_in[4];
    const float* qnw   = (const float*)d_in[5];
    const float* qnb   = (const float*)d_in[6];
    const float* knw   = (const float*)d_in[7];
    const float* knb   = (const float*)d_in[8];
    const float* projw = (const float*)d_in[9];
    const float* projb = (const float*)d_in[10];
    const float* g1    = (const float*)d_in[11];
    const float* n2w   = (const float*)d_in[12];
    const float* n2b   = (const float*)d_in[13];
    const float* fc1w  = (const float*)d_in[14];
    const float* fc1b  = (const float*)d_in[15];
    const float* mnw   = (const float*)d_in[16];
    const float* mnb   = (const float*)d_in[17];
    const float* fc2w  = (const float*)d_in[18];
    const float* fc2b  = (const float*)d_in[19];
    const float* g2    = (const float*)d_in[20];
    float* out = (float*)d_out;

    cudaFuncSetAttribute(kA,   cudaFuncAttributeMaxDynamicSharedMemorySize, SMEM_A);
    cudaFuncSetAttribute(kB,   cudaFuncAttributeMaxDynamicSharedMemorySize, SMEM_B);
    cudaFuncSetAttribute(kCDE, cudaFuncAttributeMaxDynamicSharedMemorySize, SMEM_F);

    kA<<<256, 384, SMEM_A>>>(x, n1w, n1b, qkvw, qkvb, qnw, qnb, knw, knb);
    kB<<<dim3(32, 8), 256, SMEM_B>>>();

    // kCDE with programmatic dependent launch: weight staging overlaps kB tail
    cudaLaunchConfig_t cfg = {};
    cfg.gridDim  = dim3(256, 1, 1);
    cfg.blockDim = dim3(256, 1, 1);
    cfg.dynamicSmemBytes = SMEM_F;
    cfg.stream = 0;
    cudaLaunchAttribute attrs[1];
    attrs[0].id = cudaLaunchAttributeProgrammaticStreamSerialization;
    attrs[0].val.programmaticStreamSerializationAllowed = 1;
    cfg.attrs = attrs;
    cfg.numAttrs = 1;
    cudaLaunchKernelEx(&cfg, kCDE, x, projw, projb, g1, n2w, n2b,
                       fc1w, fc1b, mnw, mnb, fc2w, fc2b, g2, out);
}